// round 1
// baseline (speedup 1.0000x reference)
#include <cuda_runtime.h>
#include <math.h>

#define NN 16800
#define KK 1024
#define NTHR 512

struct Smem {
    unsigned long long mask[KK * 16];   // suppression bitmask rows
    unsigned long long cand[KK];        // (okey<<32) | ~idx
    float4 box[KK];
    float kpt[KK * 10];
    float val[KK];
    float area[KK];
    float mult[KK];
    unsigned int hist[256];
    int wsum[16];
    unsigned int pref;
    int kr;
    int cntgt;
    int eqbase;
};

__global__ __launch_bounds__(NTHR, 1)
void nms_kernel(const float* __restrict__ p_loc,
                const float* __restrict__ p_conf,
                const float* __restrict__ p_landms,
                const float* __restrict__ anchors,
                float* __restrict__ out)
{
    extern __shared__ char raw[];
    Smem* s = reinterpret_cast<Smem*>(raw);
    const int b = blockIdx.x;
    const int tid = threadIdx.x;
    const float* conf = p_conf + (size_t)b * NN;

    if (tid == 0) { s->pref = 0u; s->kr = KK; s->cntgt = 0; s->eqbase = 0; }

    // ---- exact radix select: find the 1024th-largest ordered key ----
    // okey: conf >= 0 (i.e. sigmoid >= 0.5) -> float bits | MSB ; filtered -> 0
    for (int pass = 0; pass < 4; pass++) {
        const int shift = 24 - 8 * pass;
        if (tid < 256) s->hist[tid] = 0u;
        __syncthreads();
        const unsigned long long prefHi = s->pref;
        for (int i = tid; i < NN; i += NTHR) {
            float c = conf[i];
            unsigned okey = (c >= 0.0f) ? (__float_as_uint(c) | 0x80000000u) : 0u;
            if ((((unsigned long long)okey) >> (shift + 8)) == prefHi)
                atomicAdd(&s->hist[(okey >> shift) & 255u], 1u);
        }
        __syncthreads();
        if (tid == 0) {
            int c = 0, kr = s->kr;
            for (int v = 255; v >= 0; v--) {
                c += (int)s->hist[v];
                if (c >= kr) {
                    s->pref = (s->pref << 8) | (unsigned)v;
                    s->kr = kr - (c - (int)s->hist[v]);
                    break;
                }
            }
        }
        __syncthreads();
    }
    const unsigned T = s->pref;
    const int need = s->kr;           // # of ==T ties to take, lowest index first
    const int eq_slot0 = KK - need;   // strictly-greater fill [0, eq_slot0)

    // ---- compaction into cand[1024] ----
    const int lane = tid & 31, wrp = tid >> 5;
    for (int base = 0; base < NN; base += NTHR) {
        int i = base + tid;
        bool valid = (i < NN);
        unsigned okey = 0u;
        if (valid) {
            float c = conf[i];
            okey = (c >= 0.0f) ? (__float_as_uint(c) | 0x80000000u) : 0u;
        }
        bool gt = valid && (okey > T);
        bool eq = valid && (okey == T);
        if (gt) {
            int p = atomicAdd(&s->cntgt, 1);
            s->cand[p] = (((unsigned long long)okey) << 32) | (unsigned)(~(unsigned)i);
        }
        unsigned bal = __ballot_sync(0xffffffffu, eq);
        if (lane == 0) s->wsum[wrp] = __popc(bal);
        __syncthreads();
        int woff = 0;
        for (int w = 0; w < wrp; w++) woff += s->wsum[w];
        int rank = s->eqbase + woff + __popc(bal & ((1u << lane) - 1u));
        if (eq && rank < need)
            s->cand[eq_slot0 + rank] = (((unsigned long long)T) << 32) | (unsigned)(~(unsigned)i);
        __syncthreads();
        if (tid == 0) {
            int tot = 0;
            for (int w = 0; w < 16; w++) tot += s->wsum[w];
            s->eqbase += tot;
        }
        __syncthreads();
    }

    // ---- bitonic sort, descending; keys are distinct 64-bit -> exact top_k order ----
    for (int k2 = 2; k2 <= KK; k2 <<= 1) {
        for (int j = k2 >> 1; j > 0; j >>= 1) {
            for (int t = tid; t < KK; t += NTHR) {
                int ixj = t ^ j;
                if (ixj > t) {
                    unsigned long long a = s->cand[t], c = s->cand[ixj];
                    bool sw = ((t & k2) == 0) ? (a < c) : (a > c);
                    if (sw) { s->cand[t] = c; s->cand[ixj] = a; }
                }
            }
            __syncthreads();
        }
    }

    // ---- gather + decode the 1024 selected rows ----
    for (int t = tid; t < KK; t += NTHR) {
        unsigned long long cd = s->cand[t];
        int idx = (int)(~(unsigned)cd);
        float c = conf[idx];
        float val = (c >= 0.0f) ? (1.0f / (1.0f + expf(-c))) : -1.0f;
        float4 a = ((const float4*)anchors)[idx];
        float4 l = ((const float4*)p_loc)[(size_t)b * NN + idx];
        float cx = a.x + l.x * 0.1f * a.z;
        float cy = a.y + l.y * 0.1f * a.w;
        float w = a.z * expf(l.z * 0.2f);
        float h = a.w * expf(l.w * 0.2f);
        float x1 = cx - w * 0.5f, y1 = cy - h * 0.5f;
        float x2 = cx + w * 0.5f, y2 = cy + h * 0.5f;
        s->box[t] = make_float4(x1, y1, x2, y2);
        s->area[t] = fmaxf(x2 - x1, 0.0f) * fmaxf(y2 - y1, 0.0f);
        s->val[t] = val;
        const float* lm = p_landms + ((size_t)b * NN + idx) * 10;
        #pragma unroll
        for (int p = 0; p < 5; p++) {
            s->kpt[t * 10 + 2 * p]     = a.x + lm[2 * p]     * 0.1f * a.z;
            s->kpt[t * 10 + 2 * p + 1] = a.y + lm[2 * p + 1] * 0.1f * a.w;
        }
    }
    __syncthreads();

    // ---- build suppression bitmask (upper triangle only: j > i) ----
    for (int t = tid; t < KK * 16; t += NTHR) {
        int w = t >> 10;          // word index 0..15
        int i = t & (KK - 1);     // row (consecutive across threads -> bj broadcast)
        unsigned long long m = 0ull;
        int jend = w * 64 + 64;
        int j0 = (w * 64 > i + 1) ? (w * 64) : (i + 1);
        if (j0 < jend) {
            float4 bi = s->box[i];
            float ai = s->area[i];
            for (int j = j0; j < jend; j++) {
                float4 bj = s->box[j];
                float lx = fmaxf(bi.x, bj.x);
                float ly = fmaxf(bi.y, bj.y);
                float rx = fminf(bi.z, bj.z);
                float ry = fminf(bi.w, bj.w);
                float ww = fmaxf(rx - lx, 0.0f);
                float hh = fmaxf(ry - ly, 0.0f);
                float inter = ww * hh;
                float iou = __fdiv_rn(inter, ai + s->area[j] - inter + 1e-9f);
                if (iou > 0.3f) m |= (1ull << (j & 63));
            }
        }
        s->mask[i * 16 + w] = m;
    }
    __syncthreads();

    // ---- sequential greedy scan (warp 0; lane l owns suppressed-word l) ----
    if (tid < 32) {
        unsigned long long rw = 0ull;
        for (int i = 0; i < KK; i++) {
            unsigned long long word = __shfl_sync(0xffffffffu, rw, i >> 6);
            bool keep = (s->val[i] >= 0.5f) && !((word >> (i & 63)) & 1ull);
            if (keep && tid < 16) rw |= s->mask[i * 16 + tid];
            if (tid == 0) s->mult[i] = keep ? 1.0f : 0.0f;
        }
    }
    __syncthreads();

    // ---- masked output rows: [ltrb(4) | kpts(10) | score(1)] * keep ----
    float* outp = out + (size_t)b * KK * 15;
    for (int e = tid; e < KK * 15; e += NTHR) {
        int r = e / 15;
        int c2 = e - r * 15;
        float m = s->mult[r];
        float v;
        if (c2 < 4)       v = ((const float*)&s->box[r])[c2];
        else if (c2 < 14) v = s->kpt[r * 10 + (c2 - 4)];
        else              v = s->val[r];
        outp[e] = v * m;
    }
}

extern "C" void kernel_launch(void* const* d_in, const int* in_sizes, int n_in,
                              void* d_out, int out_size) {
    const float* p_loc    = (const float*)d_in[0];
    const float* p_conf   = (const float*)d_in[1];
    const float* p_landms = (const float*)d_in[2];
    const float* anchors  = (const float*)d_in[3];
    cudaFuncSetAttribute(nms_kernel, cudaFuncAttributeMaxDynamicSharedMemorySize,
                         (int)sizeof(Smem));
    nms_kernel<<<64, NTHR, sizeof(Smem)>>>(p_loc, p_conf, p_landms, anchors,
                                           (float*)d_out);
}

// round 2
// speedup vs baseline: 1.6839x; 1.6839x over previous
#include <cuda_runtime.h>
#include <math.h>

#define NN 16800
#define KK 1024
#define BB 64
#define NT1 1024
#define NT2 256
#define NT3 1024

// ---- device-global scratch (allocation-free workaround) ----
__device__ float4             g_box [BB * KK];
__device__ float              g_area[BB * KK];
__device__ float              g_val [BB * KK];
__device__ float              g_kpt [BB * KK * 10];
__device__ unsigned long long g_mask[(size_t)BB * KK * 16];

// ================= Kernel 1: exact radix top-K select + sort + decode =================
struct S1 {
    unsigned okey[NN];
    unsigned long long cand[KK];
    unsigned hist[256];
    int wsum[32];
    unsigned pref;
    int kr;
    int cntgt;
};

__global__ __launch_bounds__(NT1, 1)
void k_select(const float* __restrict__ p_loc,
              const float* __restrict__ p_conf,
              const float* __restrict__ p_landms,
              const float* __restrict__ anchors)
{
    extern __shared__ char raw[];
    S1* s = reinterpret_cast<S1*>(raw);
    const int b = blockIdx.x, tid = threadIdx.x;
    const int lane = tid & 31, wrp = tid >> 5;
    const float* conf = p_conf + (size_t)b * NN;

    if (tid == 0) { s->pref = 0u; s->kr = KK; s->cntgt = 0; }
    if (tid < 256) s->hist[tid] = 0u;
    __syncthreads();

    // pass 0: compute ordered keys into smem + histogram top byte
    // okey: conf>=0 (sigmoid>=0.5) -> bits|MSB ; filtered -> 0
    for (int base = 0; base < NN; base += NT1) {
        int i = base + tid;
        bool v = (i < NN);
        unsigned ok = 0u;
        if (v) {
            float c = conf[i];
            ok = (c >= 0.0f) ? (__float_as_uint(c) | 0x80000000u) : 0u;
            s->okey[i] = ok;
        }
        unsigned bucket = v ? (ok >> 24) : 0xFFFFFFFFu;
        unsigned grp = __match_any_sync(0xffffffffu, bucket);
        if (v && lane == (__ffs(grp) - 1))
            atomicAdd(&s->hist[bucket], (unsigned)__popc(grp));
    }
    __syncthreads();
    if (tid == 0) {
        int c = 0, kr = s->kr;
        for (int v = 255; v >= 0; v--) {
            c += (int)s->hist[v];
            if (c >= kr) { s->pref = (unsigned)v; s->kr = kr - (c - (int)s->hist[v]); break; }
        }
    }
    __syncthreads();

    // passes 1..3 over smem-cached keys
    for (int pass = 1; pass < 4; pass++) {
        const int shift = 24 - 8 * pass;
        const unsigned prefHi = s->pref;
        __syncthreads();
        if (tid < 256) s->hist[tid] = 0u;
        __syncthreads();
        for (int base = 0; base < NN; base += NT1) {
            int i = base + tid;
            bool v = (i < NN);
            unsigned ok = v ? s->okey[i] : 0u;
            bool part = v && ((ok >> (shift + 8)) == prefHi);
            unsigned bucket = part ? ((ok >> shift) & 255u) : 0xFFFFFFFFu;
            unsigned grp = __match_any_sync(0xffffffffu, bucket);
            if (part && lane == (__ffs(grp) - 1))
                atomicAdd(&s->hist[bucket], (unsigned)__popc(grp));
        }
        __syncthreads();
        if (tid == 0) {
            int c = 0, kr = s->kr;
            for (int v = 255; v >= 0; v--) {
                c += (int)s->hist[v];
                if (c >= kr) { s->pref = (s->pref << 8) | (unsigned)v; s->kr = kr - (c - (int)s->hist[v]); break; }
            }
        }
        __syncthreads();
    }
    const unsigned T = s->pref;
    const int need = s->kr;          // # of ==T ties to take, lowest index first
    const int eq0 = KK - need;       // strictly-greater items fill [0, eq0)

    // ---- compaction (stable for ties) ----
    int eqbase = 0;
    for (int base = 0; base < NN; base += NT1) {
        int i = base + tid;
        bool v = (i < NN);
        unsigned ok = v ? s->okey[i] : 0u;
        bool gt = v && (ok > T);
        bool eq = v && (ok == T);
        if (gt) {
            int p = atomicAdd(&s->cntgt, 1);
            s->cand[p] = (((unsigned long long)ok) << 32) | (unsigned)(~(unsigned)i);
        }
        unsigned bal = __ballot_sync(0xffffffffu, eq);
        if (lane == 0) s->wsum[wrp] = __popc(bal);
        __syncthreads();
        int woff = 0, tot = 0;
        #pragma unroll
        for (int w = 0; w < 32; w++) { int x = s->wsum[w]; if (w < wrp) woff += x; tot += x; }
        int rank = eqbase + woff + __popc(bal & ((1u << lane) - 1u));
        if (eq && rank < need)
            s->cand[eq0 + rank] = (((unsigned long long)T) << 32) | (unsigned)(~(unsigned)i);
        eqbase += tot;
        __syncthreads();
    }

    // ---- bitonic sort descending; distinct 64-bit keys -> exact top_k order ----
    for (int k2 = 2; k2 <= KK; k2 <<= 1) {
        for (int j = k2 >> 1; j > 0; j >>= 1) {
            int t = tid, ixj = t ^ j;
            if (ixj > t) {
                unsigned long long a = s->cand[t], c = s->cand[ixj];
                bool sw = ((t & k2) == 0) ? (a < c) : (a > c);
                if (sw) { s->cand[t] = c; s->cand[ixj] = a; }
            }
            __syncthreads();
        }
    }

    // ---- gather + decode 1024 selected rows -> global scratch ----
    {
        int t = tid;  // NT1 == KK
        unsigned long long cd = s->cand[t];
        int idx = (int)(~(unsigned)cd);
        float c = conf[idx];
        float val = (c >= 0.0f) ? (1.0f / (1.0f + expf(-c))) : -1.0f;
        float4 a = ((const float4*)anchors)[idx];
        float4 l = ((const float4*)p_loc)[(size_t)b * NN + idx];
        float cx = a.x + l.x * 0.1f * a.z;
        float cy = a.y + l.y * 0.1f * a.w;
        float w = a.z * expf(l.z * 0.2f);
        float h = a.w * expf(l.w * 0.2f);
        float x1 = cx - w * 0.5f, y1 = cy - h * 0.5f;
        float x2 = cx + w * 0.5f, y2 = cy + h * 0.5f;
        g_box[b * KK + t] = make_float4(x1, y1, x2, y2);
        g_area[b * KK + t] = fmaxf(x2 - x1, 0.0f) * fmaxf(y2 - y1, 0.0f);
        g_val[b * KK + t] = val;
        const float* lm = p_landms + ((size_t)b * NN + idx) * 10;
        #pragma unroll
        for (int p = 0; p < 5; p++) {
            g_kpt[(b * KK + t) * 10 + 2 * p]     = a.x + lm[2 * p]     * 0.1f * a.z;
            g_kpt[(b * KK + t) * 10 + 2 * p + 1] = a.y + lm[2 * p + 1] * 0.1f * a.w;
        }
    }
}

// ================= Kernel 2: suppression bitmask build (full-chip) =================
__global__ __launch_bounds__(NT2)
void k_mask()
{
    __shared__ float4 cb[64];
    __shared__ float  ca[64];
    const int w = blockIdx.x;     // word group 0..15
    const int b = blockIdx.y;     // image
    const int tid = threadIdx.x;
    const float4* box = g_box + b * KK;
    const float*  area = g_area + b * KK;

    if (tid < 64) { cb[tid] = box[w * 64 + tid]; ca[tid] = area[w * 64 + tid]; }
    __syncthreads();

    for (int i = tid; i < KK; i += NT2) {
        unsigned long long m = 0ull;
        int j0 = (w * 64 > i + 1) ? (w * 64) : (i + 1);
        int l0 = j0 - w * 64;
        if (l0 < 64) {
            float4 bi = box[i];
            float ai = area[i];
            for (int l = l0; l < 64; l++) {
                float4 bj = cb[l];
                float lx = fmaxf(bi.x, bj.x);
                float ly = fmaxf(bi.y, bj.y);
                float rx = fminf(bi.z, bj.z);
                float ry = fminf(bi.w, bj.w);
                float ww = fmaxf(rx - lx, 0.0f);
                float hh = fmaxf(ry - ly, 0.0f);
                float inter = ww * hh;
                float iou = __fdiv_rn(inter, ai + ca[l] - inter + 1e-9f);
                if (iou > 0.3f) m |= (1ull << l);
            }
        }
        g_mask[((size_t)b * KK + i) * 16 + w] = m;
    }
}

// ================= Kernel 3: greedy scan + masked output =================
struct S3 {
    unsigned long long mask[KK * 16];
    float val[KK];
    float mult[KK];
};

__global__ __launch_bounds__(NT3, 1)
void k_scan(float* __restrict__ out)
{
    extern __shared__ char raw[];
    S3* s = reinterpret_cast<S3*>(raw);
    const int b = blockIdx.x, tid = threadIdx.x;

    const unsigned long long* gm = g_mask + (size_t)b * KK * 16;
    for (int t = tid; t < KK * 16; t += NT3) s->mask[t] = gm[t];
    for (int t = tid; t < KK; t += NT3) s->val[t] = g_val[b * KK + t];
    __syncthreads();

    if (tid == 0) {
        unsigned long long rw[16];
        #pragma unroll
        for (int c = 0; c < 16; c++) rw[c] = 0ull;
        #pragma unroll
        for (int c = 0; c < 16; c++) {
            unsigned long long w = rw[c];
            for (int r = 0; r < 64; r++) {
                int i = c * 64 + r;
                bool keep = (s->val[i] >= 0.5f) && !((w >> r) & 1ull);
                s->mult[i] = keep ? 1.0f : 0.0f;
                if (keep) {
                    const unsigned long long* mr = &s->mask[i * 16];
                    w |= mr[c];                     // critical-path word only
                    #pragma unroll
                    for (int l = 0; l < 16; l++)    // future chunks, off critical path
                        if (l > c) rw[l] |= mr[l];
                }
            }
        }
    }
    __syncthreads();

    const float4* box = g_box + b * KK;
    const float*  kpt = g_kpt + (size_t)b * KK * 10;
    float* outp = out + (size_t)b * KK * 15;
    for (int e = tid; e < KK * 15; e += NT3) {
        int r = e / 15;
        int c2 = e - r * 15;
        float m = s->mult[r];
        float v;
        if (c2 < 4)       v = ((const float*)&box[r])[c2];
        else if (c2 < 14) v = kpt[r * 10 + (c2 - 4)];
        else              v = s->val[r];
        outp[e] = v * m;
    }
}

extern "C" void kernel_launch(void* const* d_in, const int* in_sizes, int n_in,
                              void* d_out, int out_size) {
    const float* p_loc    = (const float*)d_in[0];
    const float* p_conf   = (const float*)d_in[1];
    const float* p_landms = (const float*)d_in[2];
    const float* anchors  = (const float*)d_in[3];

    cudaFuncSetAttribute(k_select, cudaFuncAttributeMaxDynamicSharedMemorySize, (int)sizeof(S1));
    cudaFuncSetAttribute(k_scan,   cudaFuncAttributeMaxDynamicSharedMemorySize, (int)sizeof(S3));

    k_select<<<BB, NT1, sizeof(S1)>>>(p_loc, p_conf, p_landms, anchors);
    k_mask<<<dim3(16, BB), NT2>>>();
    k_scan<<<BB, NT3, sizeof(S3)>>>((float*)d_out);
}

// round 3
// speedup vs baseline: 3.9275x; 2.3324x over previous
#include <cuda_runtime.h>
#include <math.h>

#define NN 16800
#define KK 1024
#define BB 64
#define NT1 1024
#define HP 257   // padded histogram pitch (bank-conflict-free)

// ---- device-global scratch (allocation-free workaround) ----
__device__ float4 g_box [BB * KK];
__device__ float  g_area[BB * KK];
__device__ float  g_val [BB * KK];
__device__ float  g_kpt [BB * KK * 10];

// ================= Kernel 1: exact radix top-K select + sort + decode =================
struct S1 {
    unsigned okey[NN];                 // ordered keys
    unsigned hist32[32 * HP];          // per-warp histograms
    unsigned long long cand[KK];
    unsigned warpsum[8];
    unsigned pref_arr[5];
    int kr_arr[5];
    int wsum[32];
    int cntgt;
    int eqtot;
};

__global__ __launch_bounds__(NT1, 1)
void k_select(const float* __restrict__ p_loc,
              const float* __restrict__ p_conf,
              const float* __restrict__ p_landms,
              const float* __restrict__ anchors)
{
    extern __shared__ char raw[];
    S1* s = reinterpret_cast<S1*>(raw);
    const int b = blockIdx.x, tid = threadIdx.x;
    const int lane = tid & 31, wrp = tid >> 5;
    const float* conf = p_conf + (size_t)b * NN;

    if (tid == 0) { s->pref_arr[0] = 0u; s->kr_arr[0] = KK; s->cntgt = 0; s->eqtot = 0; }

    // ================= 4 radix passes (8 bits each) =================
    #pragma unroll
    for (int p = 0; p < 4; p++) {
        const int shift = 24 - 8 * p;
        // zero per-warp histograms
        for (int t = tid; t < 32 * HP; t += NT1) s->hist32[t] = 0u;
        __syncthreads();
        const unsigned prefv = s->pref_arr[p];
        const int krloc = s->kr_arr[p];

        for (int base = 0; base < NN; base += NT1) {
            int i = base + tid;
            bool v = (i < NN);
            unsigned ok = 0u;
            if (p == 0) {
                if (v) {
                    float c = conf[i];
                    ok = (c >= 0.0f) ? (__float_as_uint(c) | 0x80000000u) : 0u;
                    s->okey[i] = ok;
                }
            } else {
                ok = v ? s->okey[i] : 0u;
            }
            bool part = v && (p == 0 || (ok >> (shift + 8)) == prefv);
            unsigned bucket = part ? ((ok >> shift) & 255u) : 0xFFFFFFFFu;
            unsigned grp = __match_any_sync(0xffffffffu, bucket);
            if (part && lane == (__ffs(grp) - 1))
                s->hist32[wrp * HP + bucket] += (unsigned)__popc(grp);
        }
        __syncthreads();

        // parallel digit find: threads 0..255 own buckets
        unsigned cnt = 0, ssum = 0;
        if (tid < 256) {
            #pragma unroll
            for (int w = 0; w < 32; w++) cnt += s->hist32[w * HP + tid];
            ssum = cnt;
            #pragma unroll
            for (int d = 1; d < 32; d <<= 1) {
                unsigned x = __shfl_down_sync(0xffffffffu, ssum, d);
                if (lane + d < 32) ssum += x;
            }
            if (lane == 0) s->warpsum[wrp] = ssum;   // whole-warp suffix total
        }
        __syncthreads();
        if (tid < 256) {
            unsigned hi = 0;
            for (int w = wrp + 1; w < 8; w++) hi += s->warpsum[w];
            unsigned S = ssum + hi;                  // suffix sum over buckets >= tid
            if (S >= (unsigned)krloc && S - cnt < (unsigned)krloc) {
                s->pref_arr[p + 1] = (prefv << 8) | (unsigned)tid;
                s->kr_arr[p + 1] = krloc - (int)(S - cnt);
                s->eqtot = (int)cnt;
            }
        }
        __syncthreads();
    }

    const unsigned T = s->pref_arr[4];
    const int need = s->kr_arr[4];     // # of ==T ties taken (lowest index first)
    const int eq0 = KK - need;
    const bool fastpath = (s->eqtot == need);

    // ================= compaction =================
    if (fastpath) {
        // all eq items taken -> order-free; two-phase warp-aggregated append
        int mycnt = 0;
        for (int base = 0; base < NN; base += NT1) {
            int i = base + tid;
            bool take = (i < NN) && (s->okey[i] >= T) && (T != 0u || true);
            take = (i < NN) && (s->okey[i] >= T);
            mycnt += __popc(__ballot_sync(0xffffffffu, take));
        }
        int wb = 0;
        if (lane == 0) wb = atomicAdd(&s->cntgt, mycnt);
        wb = __shfl_sync(0xffffffffu, wb, 0);
        for (int base = 0; base < NN; base += NT1) {
            int i = base + tid;
            bool take = (i < NN) && (s->okey[i] >= T);
            unsigned bal = __ballot_sync(0xffffffffu, take);
            if (take) {
                int pos = wb + __popc(bal & ((1u << lane) - 1u));
                s->cand[pos] = (((unsigned long long)s->okey[i]) << 32) | (unsigned)(~(unsigned)i);
            }
            wb += __popc(bal);
        }
        __syncthreads();
    } else {
        // rare: ties beyond cutoff -> stable (lowest-index) eq selection
        int eqbase = 0;
        for (int base = 0; base < NN; base += NT1) {
            int i = base + tid;
            bool v = (i < NN);
            unsigned ok = v ? s->okey[i] : 0u;
            bool gt = v && (ok > T);
            bool eq = v && (ok == T);
            if (gt) {
                int p2 = atomicAdd(&s->cntgt, 1);
                s->cand[p2] = (((unsigned long long)ok) << 32) | (unsigned)(~(unsigned)i);
            }
            unsigned bal = __ballot_sync(0xffffffffu, eq);
            if (lane == 0) s->wsum[wrp] = __popc(bal);
            __syncthreads();
            int woff = 0, tot = 0;
            #pragma unroll
            for (int w = 0; w < 32; w++) { int x = s->wsum[w]; if (w < wrp) woff += x; tot += x; }
            int rank = eqbase + woff + __popc(bal & ((1u << lane) - 1u));
            if (eq && rank < need)
                s->cand[eq0 + rank] = (((unsigned long long)T) << 32) | (unsigned)(~(unsigned)i);
            eqbase += tot;
            __syncthreads();
        }
    }

    // ================= bitonic sort, descending (distinct 64-bit keys) =================
    for (int k2 = 2; k2 <= KK; k2 <<= 1) {
        for (int j = k2 >> 1; j > 0; j >>= 1) {
            int t = tid, ixj = t ^ j;
            if (ixj > t) {
                unsigned long long a = s->cand[t], c = s->cand[ixj];
                bool sw = ((t & k2) == 0) ? (a < c) : (a > c);
                if (sw) { s->cand[t] = c; s->cand[ixj] = a; }
            }
            __syncthreads();
        }
    }

    // ================= gather + decode 1024 rows -> global scratch =================
    {
        int t = tid;  // NT1 == KK
        unsigned long long cd = s->cand[t];
        int idx = (int)(~(unsigned)cd);
        unsigned ok = (unsigned)(cd >> 32);
        float c = __uint_as_float(ok & 0x7FFFFFFFu);
        float val = (ok != 0u) ? (1.0f / (1.0f + expf(-c))) : -1.0f;
        float4 a = ((const float4*)anchors)[idx];
        float4 l = ((const float4*)p_loc)[(size_t)b * NN + idx];
        float cx = a.x + l.x * 0.1f * a.z;
        float cy = a.y + l.y * 0.1f * a.w;
        float w = a.z * expf(l.z * 0.2f);
        float h = a.w * expf(l.w * 0.2f);
        float x1 = cx - w * 0.5f, y1 = cy - h * 0.5f;
        float x2 = cx + w * 0.5f, y2 = cy + h * 0.5f;
        g_box[b * KK + t] = make_float4(x1, y1, x2, y2);
        g_area[b * KK + t] = fmaxf(x2 - x1, 0.0f) * fmaxf(y2 - y1, 0.0f);
        g_val[b * KK + t] = val;
        const float* lm = p_landms + ((size_t)b * NN + idx) * 10;
        #pragma unroll
        for (int p2 = 0; p2 < 5; p2++) {
            g_kpt[(b * KK + t) * 10 + 2 * p2]     = a.x + lm[2 * p2]     * 0.1f * a.z;
            g_kpt[(b * KK + t) * 10 + 2 * p2 + 1] = a.y + lm[2 * p2 + 1] * 0.1f * a.w;
        }
    }
}

// ================= Kernel 2: pivot-driven greedy NMS + output =================
__global__ __launch_bounds__(NT1, 1)
void k_nms(float* __restrict__ out)
{
    __shared__ float4 sbox[KK];
    __shared__ float  sarea[KK];
    __shared__ float  sval[KK];
    __shared__ float  smult[KK];
    __shared__ int    s_next;

    const int b = blockIdx.x, tid = threadIdx.x;

    float4 bj = g_box[b * KK + tid];
    float  aj = g_area[b * KK + tid];
    float  vj = g_val[b * KK + tid];
    sbox[tid] = bj; sarea[tid] = aj; sval[tid] = vj;
    smult[tid] = (vj >= 0.5f) ? 1.0f : 0.0f;   // alive = conf-pass, not yet suppressed
    __syncthreads();

    int i = -1;
    while (true) {
        if (tid < 32) {   // warp 0 finds next alive pivot
            int nx = KK;
            for (int basei = i + 1; basei < KK; basei += 32) {
                int ii = basei + tid;
                bool alive = (ii < KK) && (smult[ii] != 0.0f);
                unsigned bal = __ballot_sync(0xffffffffu, alive);
                if (bal) { nx = basei + __ffs(bal) - 1; break; }
            }
            if (tid == 0) s_next = nx;
        }
        __syncthreads();
        i = s_next;
        if (i >= KK) break;

        float4 bi = sbox[i];
        float  ai = sarea[i];
        if (tid > i && smult[tid] != 0.0f) {
            float lx = fmaxf(bi.x, bj.x);
            float ly = fmaxf(bi.y, bj.y);
            float rx = fminf(bi.z, bj.z);
            float ry = fminf(bi.w, bj.w);
            float ww = fmaxf(rx - lx, 0.0f);
            float hh = fmaxf(ry - ly, 0.0f);
            float inter = ww * hh;
            float iou = __fdiv_rn(inter, ai + aj - inter + 1e-9f);
            if (iou > 0.3f) smult[tid] = 0.0f;
        }
        __syncthreads();
    }

    // masked output rows: [ltrb(4) | kpts(10) | score(1)] * keep
    const float* kpt = g_kpt + (size_t)b * KK * 10;
    float* outp = out + (size_t)b * KK * 15;
    for (int e = tid; e < KK * 15; e += NT1) {
        int r = e / 15;
        int c2 = e - r * 15;
        float m = smult[r];
        float v;
        if (c2 < 4)       v = ((const float*)&sbox[r])[c2];
        else if (c2 < 14) v = kpt[r * 10 + (c2 - 4)];
        else              v = sval[r];
        outp[e] = v * m;
    }
}

extern "C" void kernel_launch(void* const* d_in, const int* in_sizes, int n_in,
                              void* d_out, int out_size) {
    const float* p_loc    = (const float*)d_in[0];
    const float* p_conf   = (const float*)d_in[1];
    const float* p_landms = (const float*)d_in[2];
    const float* anchors  = (const float*)d_in[3];

    cudaFuncSetAttribute(k_select, cudaFuncAttributeMaxDynamicSharedMemorySize, (int)sizeof(S1));

    k_select<<<BB, NT1, sizeof(S1)>>>(p_loc, p_conf, p_landms, anchors);
    k_nms<<<BB, NT1>>>((float*)d_out);
}

// round 4
// speedup vs baseline: 4.1645x; 1.0603x over previous
#include <cuda_runtime.h>
#include <math.h>

#define NN 16800
#define KK 1024
#define BB 64
#define NT 1024
#define HP 257   // padded per-warp histogram pitch

struct SF {
    union {
        struct {                       // select phase
            unsigned okey[NN];         // 67200 B
            unsigned hist32[32 * HP];  // 32896 B
        } a;
        struct {                       // nms phase
            float4 sbox[KK];           // 16384
            float  sarea[KK];          //  4096
            float  sval[KK];           //  4096
            float  smult[KK];          //  4096
            unsigned long long smask[KK]; // 8192 (intra-chunk row masks)
            float  skpt[KK * 10];      // 40960
        } n;
    } u;
    unsigned long long cand[KK];       // 8192
    unsigned long long s_kept;
    unsigned warpsum[8];
    unsigned pref_arr[5];
    int kr_arr[5];
    int wsum[32];
    int cntgt;
    int eqtot;
};

__global__ __launch_bounds__(NT, 1)
void k_fused(const float* __restrict__ p_loc,
             const float* __restrict__ p_conf,
             const float* __restrict__ p_landms,
             const float* __restrict__ anchors,
             float* __restrict__ out)
{
    extern __shared__ char raw[];
    SF* s = reinterpret_cast<SF*>(raw);
    const int b = blockIdx.x, tid = threadIdx.x;
    const int lane = tid & 31, wrp = tid >> 5;
    const float* conf = p_conf + (size_t)b * NN;

    if (tid == 0) { s->pref_arr[0] = 0u; s->kr_arr[0] = KK; s->cntgt = 0; s->eqtot = 0; }

    // ================= exact radix top-K threshold (4x8-bit passes) =================
    #pragma unroll
    for (int p = 0; p < 4; p++) {
        const int shift = 24 - 8 * p;
        for (int t = tid; t < 32 * HP; t += NT) s->u.a.hist32[t] = 0u;
        __syncthreads();
        const unsigned prefv = s->pref_arr[p];
        const int krloc = s->kr_arr[p];

        for (int base = 0; base < NN; base += NT) {
            int i = base + tid;
            bool v = (i < NN);
            unsigned ok = 0u;
            if (p == 0) {
                if (v) {
                    float c = conf[i];
                    ok = (c >= 0.0f) ? (__float_as_uint(c) | 0x80000000u) : 0u;
                    s->u.a.okey[i] = ok;
                }
            } else {
                ok = v ? s->u.a.okey[i] : 0u;
            }
            bool part = v && (p == 0 || (ok >> (shift + 8)) == prefv);
            unsigned bucket = part ? ((ok >> shift) & 255u) : 0xFFFFFFFFu;
            unsigned grp = __match_any_sync(0xffffffffu, bucket);
            if (part && lane == (__ffs(grp) - 1))
                s->u.a.hist32[wrp * HP + bucket] += (unsigned)__popc(grp);
        }
        __syncthreads();

        unsigned cnt = 0, ssum = 0;
        if (tid < 256) {
            #pragma unroll
            for (int w = 0; w < 32; w++) cnt += s->u.a.hist32[w * HP + tid];
            ssum = cnt;
            #pragma unroll
            for (int d = 1; d < 32; d <<= 1) {
                unsigned x = __shfl_down_sync(0xffffffffu, ssum, d);
                if (lane + d < 32) ssum += x;
            }
            if (lane == 0) s->warpsum[wrp] = ssum;
        }
        __syncthreads();
        if (tid < 256) {
            unsigned hi = 0;
            for (int w = wrp + 1; w < 8; w++) hi += s->warpsum[w];
            unsigned S = ssum + hi;      // suffix sum over buckets >= tid
            if (S >= (unsigned)krloc && S - cnt < (unsigned)krloc) {
                s->pref_arr[p + 1] = (prefv << 8) | (unsigned)tid;
                s->kr_arr[p + 1] = krloc - (int)(S - cnt);
                s->eqtot = (int)cnt;
            }
        }
        __syncthreads();
    }

    const unsigned T = s->pref_arr[4];
    const int need = s->kr_arr[4];
    const int eq0 = KK - need;
    const bool fastpath = (s->eqtot == need);

    // ================= compaction =================
    if (fastpath) {
        int mycnt = 0;
        for (int base = 0; base < NN; base += NT) {
            int i = base + tid;
            bool take = (i < NN) && (s->u.a.okey[i] >= T);
            mycnt += __popc(__ballot_sync(0xffffffffu, take));
        }
        int wb = 0;
        if (lane == 0) wb = atomicAdd(&s->cntgt, mycnt);
        wb = __shfl_sync(0xffffffffu, wb, 0);
        for (int base = 0; base < NN; base += NT) {
            int i = base + tid;
            bool take = (i < NN) && (s->u.a.okey[i] >= T);
            unsigned bal = __ballot_sync(0xffffffffu, take);
            if (take) {
                int pos = wb + __popc(bal & ((1u << lane) - 1u));
                s->cand[pos] = (((unsigned long long)s->u.a.okey[i]) << 32) | (unsigned)(~(unsigned)i);
            }
            wb += __popc(bal);
        }
        __syncthreads();
    } else {
        int eqbase = 0;
        for (int base = 0; base < NN; base += NT) {
            int i = base + tid;
            bool v = (i < NN);
            unsigned ok = v ? s->u.a.okey[i] : 0u;
            bool gt = v && (ok > T);
            bool eq = v && (ok == T);
            if (gt) {
                int p2 = atomicAdd(&s->cntgt, 1);
                s->cand[p2] = (((unsigned long long)ok) << 32) | (unsigned)(~(unsigned)i);
            }
            unsigned bal = __ballot_sync(0xffffffffu, eq);
            if (lane == 0) s->wsum[wrp] = __popc(bal);
            __syncthreads();
            int woff = 0, tot = 0;
            #pragma unroll
            for (int w = 0; w < 32; w++) { int x = s->wsum[w]; if (w < wrp) woff += x; tot += x; }
            int rank = eqbase + woff + __popc(bal & ((1u << lane) - 1u));
            if (eq && rank < need)
                s->cand[eq0 + rank] = (((unsigned long long)T) << 32) | (unsigned)(~(unsigned)i);
            eqbase += tot;
            __syncthreads();
        }
    }

    // ================= bitonic sort descending (distinct 64-bit keys) =================
    for (int k2 = 2; k2 <= KK; k2 <<= 1) {
        for (int j = k2 >> 1; j > 0; j >>= 1) {
            int t = tid, ixj = t ^ j;
            if (ixj > t) {
                unsigned long long a = s->cand[t], c = s->cand[ixj];
                bool sw = ((t & k2) == 0) ? (a < c) : (a > c);
                if (sw) { s->cand[t] = c; s->cand[ixj] = a; }
            }
            __syncthreads();
        }
    }
    __syncthreads();   // select scratch (union .a) dead after this point

    // ================= gather + decode into smem (union .n) =================
    float4 bj; float aj; float vj;
    {
        int t = tid;
        unsigned long long cd = s->cand[t];
        int idx = (int)(~(unsigned)cd);
        unsigned ok = (unsigned)(cd >> 32);
        float c = __uint_as_float(ok & 0x7FFFFFFFu);
        vj = (ok != 0u) ? (1.0f / (1.0f + expf(-c))) : -1.0f;
        float4 a = ((const float4*)anchors)[idx];
        float4 l = ((const float4*)p_loc)[(size_t)b * NN + idx];
        float cx = a.x + l.x * 0.1f * a.z;
        float cy = a.y + l.y * 0.1f * a.w;
        float w = a.z * expf(l.z * 0.2f);
        float h = a.w * expf(l.w * 0.2f);
        float x1 = cx - w * 0.5f, y1 = cy - h * 0.5f;
        float x2 = cx + w * 0.5f, y2 = cy + h * 0.5f;
        bj = make_float4(x1, y1, x2, y2);
        aj = fmaxf(x2 - x1, 0.0f) * fmaxf(y2 - y1, 0.0f);
        s->u.n.sbox[t] = bj;
        s->u.n.sarea[t] = aj;
        s->u.n.sval[t] = vj;
        s->u.n.smult[t] = (ok != 0u) ? 1.0f : 0.0f;
        const float* lm = p_landms + ((size_t)b * NN + idx) * 10;
        #pragma unroll
        for (int p2 = 0; p2 < 5; p2++) {
            s->u.n.skpt[t * 10 + 2 * p2]     = a.x + lm[2 * p2]     * 0.1f * a.z;
            s->u.n.skpt[t * 10 + 2 * p2 + 1] = a.y + lm[2 * p2 + 1] * 0.1f * a.w;
        }
    }
    __syncthreads();

    // ================= Phase A: intra-chunk 64x64 suppression masks =================
    {
        int t64 = tid & 63, base = tid & ~63;
        unsigned long long m = 0ull;
        for (int j = t64 + 1; j < 64; j++) {
            float4 bq = s->u.n.sbox[base + j];
            float  aq = s->u.n.sarea[base + j];
            float lx = fmaxf(bj.x, bq.x);
            float ly = fmaxf(bj.y, bq.y);
            float rx = fminf(bj.z, bq.z);
            float ry = fminf(bj.w, bq.w);
            float ww = fmaxf(rx - lx, 0.0f);
            float hh = fmaxf(ry - ly, 0.0f);
            float inter = ww * hh;
            float iou = __fdiv_rn(inter, aj + aq - inter + 1e-9f);
            if (iou > 0.3f) m |= (1ull << j);
        }
        s->u.n.smask[tid] = m;
    }
    __syncthreads();

    // ================= Phase B: 16 sequential chunks =================
    #pragma unroll 1
    for (int c = 0; c < 16; c++) {
        if (tid < 32) {   // warp 0: ffs-skip scan (steps only on kept rows)
            int r0 = c * 64 + tid, r1 = r0 + 32;
            unsigned blo = __ballot_sync(0xffffffffu, s->u.n.smult[r0] != 0.0f);
            unsigned bhi = __ballot_sync(0xffffffffu, s->u.n.smult[r1] != 0.0f);
            unsigned long long a = (unsigned long long)blo | ((unsigned long long)bhi << 32);
            unsigned long long mlo = s->u.n.smask[r0];
            unsigned long long mhi = s->u.n.smask[r1];
            unsigned long long kept = 0ull;
            while (a) {
                int t = __ffsll((long long)a) - 1;
                kept |= (1ull << t);
                unsigned long long mrow = (t < 32)
                    ? __shfl_sync(0xffffffffu, mlo, t)
                    : __shfl_sync(0xffffffffu, mhi, t - 32);
                a &= ~(mrow | (1ull << t));
            }
            s->u.n.smult[r0] = ((kept >> tid) & 1ull) ? 1.0f : 0.0f;
            s->u.n.smult[r1] = ((kept >> (tid + 32)) & 1ull) ? 1.0f : 0.0f;
            if (tid == 0) s->s_kept = kept;
        }
        __syncthreads();
        if (tid >= (c + 1) * 64 && s->u.n.smult[tid] != 0.0f) {
            unsigned long long k = s->s_kept;
            while (k) {
                int t = __ffsll((long long)k) - 1;
                k &= k - 1;
                int pi = c * 64 + t;
                float4 bi = s->u.n.sbox[pi];
                float  ai = s->u.n.sarea[pi];
                float lx = fmaxf(bi.x, bj.x);
                float ly = fmaxf(bi.y, bj.y);
                float rx = fminf(bi.z, bj.z);
                float ry = fminf(bi.w, bj.w);
                float ww = fmaxf(rx - lx, 0.0f);
                float hh = fmaxf(ry - ly, 0.0f);
                float inter = ww * hh;
                float iou = __fdiv_rn(inter, ai + aj - inter + 1e-9f);
                if (iou > 0.3f) { s->u.n.smult[tid] = 0.0f; break; }
            }
        }
        __syncthreads();
    }

    // ================= masked output: [ltrb(4) | kpts(10) | score(1)] * keep =================
    float* outp = out + (size_t)b * KK * 15;
    for (int e = tid; e < KK * 15; e += NT) {
        int r = e / 15;
        int c2 = e - r * 15;
        float m = s->u.n.smult[r];
        float v;
        if (c2 < 4)       v = ((const float*)&s->u.n.sbox[r])[c2];
        else if (c2 < 14) v = s->u.n.skpt[r * 10 + (c2 - 4)];
        else              v = s->u.n.sval[r];
        outp[e] = v * m;
    }
}

extern "C" void kernel_launch(void* const* d_in, const int* in_sizes, int n_in,
                              void* d_out, int out_size) {
    const float* p_loc    = (const float*)d_in[0];
    const float* p_conf   = (const float*)d_in[1];
    const float* p_landms = (const float*)d_in[2];
    const float* anchors  = (const float*)d_in[3];

    cudaFuncSetAttribute(k_fused, cudaFuncAttributeMaxDynamicSharedMemorySize, (int)sizeof(SF));
    k_fused<<<BB, NT, sizeof(SF)>>>(p_loc, p_conf, p_landms, anchors, (float*)d_out);
}